// round 3
// baseline (speedup 1.0000x reference)
#include <cuda_runtime.h>

// Demolition_Conv2d: grouped conv (16 groups of 1->32, 3x3, pad 1) + bias,
// per-(cin,cout) 5-bit quant-dequant (scale=15/9), sum over cin.
//
// R3: latency/issue-bound fix.
//  - 2x threads: each thread does 4 pixels x 8 couts (was 16) -> 784 blocks,
//    5.3 warps/SMSP for latency hiding.
//  - In-place packed asm ("+l") to eliminate register-pair MOV traffic.

#define CIN  16
#define COUT 32
#define HH   112
#define WW   112

typedef unsigned long long f2;

__device__ __forceinline__ f2 pk2(float lo, float hi) {
    f2 r; asm("mov.b64 %0, {%1, %2};" : "=l"(r) : "f"(lo), "f"(hi)); return r;
}
// in-place: acc = a*b + acc
__device__ __forceinline__ void fma2i(f2& acc, f2 a, f2 b) {
    asm("fma.rn.f32x2 %0, %1, %2, %0;" : "+l"(acc) : "l"(a), "l"(b));
}
// in-place: acc = acc + b
__device__ __forceinline__ void add2i(f2& acc, f2 b) {
    asm("add.rn.f32x2 %0, %0, %1;" : "+l"(acc) : "l"(b));
}
__device__ __forceinline__ f2 mul2(f2 a, f2 b) {
    f2 d; asm("mul.rn.f32x2 %0, %1, %2;" : "=l"(d) : "l"(a), "l"(b)); return d;
}

#define NC 8   // couts per thread

__global__ __launch_bounds__(128)
void demolition_conv2d_kernel(const float* __restrict__ x,
                              const float* __restrict__ Wt,
                              const float* __restrict__ bias,
                              float* __restrict__ out)
{
    // This block's 8 couts: [w0..w8, bias]*SCALE, duplicated pairs.
    __shared__ __align__(16) f2 sW[CIN * NC * 10];   // 10 KB

    const float SCALEf = 15.0f / 9.0f;
    const float INVf   = 9.0f / 15.0f;
    const float MAGICf = 12582912.0f;   // 1.5 * 2^23

    // g in [0, 100352). Quarter = g/25088, uniform per block (196 blocks each).
    int g = blockIdx.x * 128 + threadIdx.x;
    int co_grp = g / 25088;             // 0..3
    int q  = g % 25088;                 // pixel-quad index
    int qw = q % 28;
    int t1 = q / 28;
    int h  = t1 % HH;
    int b  = t1 / HH;
    int w0 = qw * 4;
    int co_base = co_grp * NC;

    for (int i = threadIdx.x; i < CIN * NC * 10; i += 128) {
        int e   = i / 10;
        int k   = i % 10;
        int cin = e / NC;
        int lc  = e % NC;
        int co  = co_base + lc;
        float v = (k < 9) ? Wt[(cin * COUT + co) * 9 + k] : bias[cin * COUT + co];
        v *= SCALEf;
        sW[i] = pk2(v, v);
    }
    __syncthreads();

    const bool up = (h > 0);
    const bool dn = (h < HH - 1);
    const bool lf = (w0 > 0);
    const bool rt = (w0 < WW - 4);

    const f2 MAG2  = pk2(MAGICf,  MAGICf);
    const f2 NMAG2 = pk2(-MAGICf, -MAGICf);
    const f2 INV2  = pk2(INVf,    INVf);

    f2 acc0[NC], acc1[NC];
#pragma unroll
    for (int c = 0; c < NC; ++c) { acc0[c] = 0ULL; acc1[c] = 0ULL; }

#pragma unroll 1
    for (int cin = 0; cin < CIN; ++cin) {
        const float* base = x + (((b * CIN + cin) * HH + h) * WW) + w0;

        // 3 rows x 6 floats (zero-padded) -> 5 shifted pairs per row.
        f2 p[3][5];
#pragma unroll
        for (int r = 0; r < 3; ++r) {
            const float* rp = base + (r - 1) * WW;
            bool rowok = (r == 0) ? up : ((r == 2) ? dn : true);
            float am1 = (rowok && lf) ? rp[-1] : 0.0f;
            float4 v  = rowok ? *reinterpret_cast<const float4*>(rp)
                              : make_float4(0.f, 0.f, 0.f, 0.f);
            float a4  = (rowok && rt) ? rp[4] : 0.0f;
            p[r][0] = pk2(am1, v.x);
            p[r][1] = pk2(v.x, v.y);
            p[r][2] = pk2(v.y, v.z);
            p[r][3] = pk2(v.z, v.w);
            p[r][4] = pk2(v.w, a4);
        }

        const ulonglong2* wbase =
            reinterpret_cast<const ulonglong2*>(&sW[cin * NC * 10]);

#pragma unroll
        for (int c = 0; c < NC; ++c) {
            ulonglong2 w01 = wbase[c * 5 + 0];
            ulonglong2 w23 = wbase[c * 5 + 1];
            ulonglong2 w45 = wbase[c * 5 + 2];
            ulonglong2 w67 = wbase[c * 5 + 3];
            ulonglong2 w8b = wbase[c * 5 + 4];   // .x = w8, .y = bias

            f2 y0 = w8b.y;
            f2 y1 = w8b.y;
            fma2i(y0, p[0][0], w01.x);  fma2i(y1, p[0][2], w01.x);
            fma2i(y0, p[0][1], w01.y);  fma2i(y1, p[0][3], w01.y);
            fma2i(y0, p[0][2], w23.x);  fma2i(y1, p[0][4], w23.x);
            fma2i(y0, p[1][0], w23.y);  fma2i(y1, p[1][2], w23.y);
            fma2i(y0, p[1][1], w45.x);  fma2i(y1, p[1][3], w45.x);
            fma2i(y0, p[1][2], w45.y);  fma2i(y1, p[1][4], w45.y);
            fma2i(y0, p[2][0], w67.x);  fma2i(y1, p[2][2], w67.x);
            fma2i(y0, p[2][1], w67.y);  fma2i(y1, p[2][3], w67.y);
            fma2i(y0, p[2][2], w8b.x);  fma2i(y1, p[2][4], w8b.x);

            // RNE round to integer, accumulate exactly.
            add2i(y0, MAG2);  add2i(y0, NMAG2);
            add2i(y1, MAG2);  add2i(y1, NMAG2);
            add2i(acc0[c], y0);
            add2i(acc1[c], y1);
        }
    }

    float* ob = out + ((b * COUT + co_base) * HH + h) * WW + w0;
#pragma unroll
    for (int c = 0; c < NC; ++c) {
        ulonglong2 v;
        v.x = mul2(acc0[c], INV2);
        v.y = mul2(acc1[c], INV2);
        *reinterpret_cast<ulonglong2*>(ob + c * HH * WW) = v;
    }
}

extern "C" void kernel_launch(void* const* d_in, const int* in_sizes, int n_in,
                              void* d_out, int out_size)
{
    const float* x    = (const float*)d_in[0];   // [8,16,112,112]
    const float* Wt   = (const float*)d_in[1];   // [16,32,1,3,3]
    const float* bias = (const float*)d_in[2];   // [16,32]
    float* out        = (float*)d_out;           // [8,32,112,112]

    demolition_conv2d_kernel<<<784, 128>>>(x, Wt, bias, out);
}

// round 4
// speedup vs baseline: 1.1479x; 1.1479x over previous
#include <cuda_runtime.h>

// Demolition_Conv2d: grouped conv (16 groups of 1->32, 3x3, pad 1) + bias,
// per-(cin,cout) 5-bit quant-dequant (scale=15/9), sum over cin.
//
// R4: LDS-wavefront-bound fix. Each thread: 8 pixels (4 f32x2 pairs) x 4 couts.
// Halves weight-LDS per FMA (5 LDS.128 now feed 36 FFMA2). Weights pre-scaled
// by SCALE in smem; RNE via magic adds; integer partials summed; one final mul.

#define CIN  16
#define COUT 32
#define HH   112
#define WW   112
#define NC   4    // couts per thread

typedef unsigned long long f2;

__device__ __forceinline__ f2 pk2(float lo, float hi) {
    f2 r; asm("mov.b64 %0, {%1, %2};" : "=l"(r) : "f"(lo), "f"(hi)); return r;
}
__device__ __forceinline__ void fma2i(f2& acc, f2 a, f2 b) {
    asm("fma.rn.f32x2 %0, %1, %2, %0;" : "+l"(acc) : "l"(a), "l"(b));
}
__device__ __forceinline__ void add2i(f2& acc, f2 b) {
    asm("add.rn.f32x2 %0, %0, %1;" : "+l"(acc) : "l"(b));
}
__device__ __forceinline__ f2 mul2(f2 a, f2 b) {
    f2 d; asm("mul.rn.f32x2 %0, %1, %2;" : "=l"(d) : "l"(a), "l"(b)); return d;
}

__global__ __launch_bounds__(128)
void demolition_conv2d_kernel(const float* __restrict__ x,
                              const float* __restrict__ Wt,
                              const float* __restrict__ bias,
                              float* __restrict__ out)
{
    // This block's 4 couts: [w0..w8, bias]*SCALE per (cin, lc), dup pairs.
    __shared__ __align__(16) f2 sW[CIN * NC * 10];   // 5 KB

    const float SCALEf = 15.0f / 9.0f;
    const float INVf   = 9.0f / 15.0f;
    const float MAGICf = 12582912.0f;   // 1.5 * 2^23

    // g in [0, 100352). 12544 8-pixel tiles; cout group uniform per block
    // (12544 / 128 = 98 blocks per group).
    int g = blockIdx.x * 128 + threadIdx.x;
    int grp = g / 12544;                // 0..7
    int t  = g % 12544;
    int tw = t % 14;                    // 112/8 tiles per row
    int t1 = t / 14;
    int h  = t1 % HH;
    int b  = t1 / HH;
    int w0 = tw * 8;
    int co_base = grp * NC;

    for (int i = threadIdx.x; i < CIN * NC * 10; i += 128) {
        int e   = i / 10;
        int k   = i % 10;
        int cin = e / NC;
        int lc  = e % NC;
        int co  = co_base + lc;
        float v = (k < 9) ? Wt[(cin * COUT + co) * 9 + k] : bias[cin * COUT + co];
        v *= SCALEf;
        sW[i] = pk2(v, v);
    }
    __syncthreads();

    const bool up = (h > 0);
    const bool dn = (h < HH - 1);
    const bool lf = (w0 > 0);
    const bool rt = (w0 < WW - 8);

    const f2 MAG2  = pk2(MAGICf,  MAGICf);
    const f2 NMAG2 = pk2(-MAGICf, -MAGICf);
    const f2 INV2  = pk2(INVf,    INVf);

    f2 acc[NC][4];
#pragma unroll
    for (int c = 0; c < NC; ++c)
#pragma unroll
        for (int j = 0; j < 4; ++j) acc[c][j] = 0ULL;

#pragma unroll 1
    for (int cin = 0; cin < CIN; ++cin) {
        const float* base = x + (((b * CIN + cin) * HH + h) * WW) + w0;

        // 3 rows x 10 floats (zero-padded) -> 9 shifted pairs per row.
        f2 p[3][9];
#pragma unroll
        for (int r = 0; r < 3; ++r) {
            const float* rp = base + (r - 1) * WW;
            bool rowok = (r == 0) ? up : ((r == 2) ? dn : true);
            float am1 = (rowok && lf) ? rp[-1] : 0.0f;
            float4 v0 = rowok ? *reinterpret_cast<const float4*>(rp)
                              : make_float4(0.f, 0.f, 0.f, 0.f);
            float4 v1 = rowok ? *reinterpret_cast<const float4*>(rp + 4)
                              : make_float4(0.f, 0.f, 0.f, 0.f);
            float a8  = (rowok && rt) ? rp[8] : 0.0f;
            p[r][0] = pk2(am1,  v0.x);
            p[r][1] = pk2(v0.x, v0.y);
            p[r][2] = pk2(v0.y, v0.z);
            p[r][3] = pk2(v0.z, v0.w);
            p[r][4] = pk2(v0.w, v1.x);
            p[r][5] = pk2(v1.x, v1.y);
            p[r][6] = pk2(v1.y, v1.z);
            p[r][7] = pk2(v1.z, v1.w);
            p[r][8] = pk2(v1.w, a8);
        }

        const ulonglong2* wbase =
            reinterpret_cast<const ulonglong2*>(&sW[cin * NC * 10]);

#pragma unroll
        for (int c = 0; c < NC; ++c) {
            ulonglong2 w01 = wbase[c * 5 + 0];
            ulonglong2 w23 = wbase[c * 5 + 1];
            ulonglong2 w45 = wbase[c * 5 + 2];
            ulonglong2 w67 = wbase[c * 5 + 3];
            ulonglong2 w8b = wbase[c * 5 + 4];   // .x = w8, .y = bias

            f2 y[4];
#pragma unroll
            for (int j = 0; j < 4; ++j) y[j] = w8b.y;

#pragma unroll
            for (int j = 0; j < 4; ++j) {
                // row 0
                fma2i(y[j], p[0][2*j + 0], w01.x);
                fma2i(y[j], p[0][2*j + 1], w01.y);
                fma2i(y[j], p[0][2*j + 2], w23.x);
                // row 1
                fma2i(y[j], p[1][2*j + 0], w23.y);
                fma2i(y[j], p[1][2*j + 1], w45.x);
                fma2i(y[j], p[1][2*j + 2], w45.y);
                // row 2
                fma2i(y[j], p[2][2*j + 0], w67.x);
                fma2i(y[j], p[2][2*j + 1], w67.y);
                fma2i(y[j], p[2][2*j + 2], w8b.x);
            }

#pragma unroll
            for (int j = 0; j < 4; ++j) {
                add2i(y[j], MAG2);
                add2i(y[j], NMAG2);
                add2i(acc[c][j], y[j]);
            }
        }
    }

    float* ob = out + ((b * COUT + co_base) * HH + h) * WW + w0;
#pragma unroll
    for (int c = 0; c < NC; ++c) {
        ulonglong2 lo, hi;
        lo.x = mul2(acc[c][0], INV2);
        lo.y = mul2(acc[c][1], INV2);
        hi.x = mul2(acc[c][2], INV2);
        hi.y = mul2(acc[c][3], INV2);
        *reinterpret_cast<ulonglong2*>(ob + c * HH * WW)     = lo;
        *reinterpret_cast<ulonglong2*>(ob + c * HH * WW + 4) = hi;
    }
}

extern "C" void kernel_launch(void* const* d_in, const int* in_sizes, int n_in,
                              void* d_out, int out_size)
{
    const float* x    = (const float*)d_in[0];   // [8,16,112,112]
    const float* Wt   = (const float*)d_in[1];   // [16,32,1,3,3]
    const float* bias = (const float*)d_in[2];   // [16,32]
    float* out        = (float*)d_out;           // [8,32,112,112]

    demolition_conv2d_kernel<<<784, 128>>>(x, Wt, bias, out);
}